// round 2
// baseline (speedup 1.0000x reference)
#include <cuda_runtime.h>
#include <cuda_bf16.h>
#include <cstdint>

// Problem constants
#define M_ROWS 224      // B*N = 32*7
#define K_DIM  49152    // 768*64
#define PRED   336
#define NBANDS 4
#define NCOLS  1344     // NBANDS*PRED
// GEMM tiling
#define BN       96
#define NTILES   14     // 1344/96
#define SPLITS   24
#define KCHUNK   2048   // 49152/24
#define KT       16
#define KITERS   128    // KCHUNK/KT
#define THREADS_G 448   // 14 warps, warp tile 16x96

// Split-K scratch (deterministic reduction; no atomics)
__device__ float g_part[SPLITS * M_ROWS * NCOLS];

// db4 reconstruction filters (REC_LO = reversed DEC_LO; REC_HI = QMF)
__constant__ float c_RL[8] = {
     0.23037781330885523f,  0.7148465705525415f,   0.6308807679295904f,
    -0.02798376941698385f, -0.18703481171888114f,  0.030841381835986965f,
     0.032883011666982945f, -0.010597401784997278f };
__constant__ float c_RH[8] = {
     0.010597401784997278f, 0.032883011666982945f, -0.030841381835986965f,
    -0.18703481171888114f,  0.02798376941698385f,   0.6308807679295904f,
    -0.7148465705525415f,   0.23037781330885523f };

__device__ __forceinline__ uint32_t ld_b32(const __nv_bfloat16* p) {
    return *reinterpret_cast<const uint32_t*>(p);
}

#define MMA_BF16(C, A0, A1, A2, A3, B0, B1)                                  \
  asm volatile(                                                              \
      "mma.sync.aligned.m16n8k16.row.col.f32.bf16.bf16.f32 "                 \
      "{%0,%1,%2,%3}, {%4,%5,%6,%7}, {%8,%9}, {%0,%1,%2,%3};\n"              \
      : "+f"(C[0]), "+f"(C[1]), "+f"(C[2]), "+f"(C[3])                       \
      : "r"(A0), "r"(A1), "r"(A2), "r"(A3), "r"(B0), "r"(B1))

// ---------------------------------------------------------------------------
// GEMM: C[224,1344] = X[224,49152] @ Wcat[49152,1344]  (split-K partials)
// fp32 inputs split into bf16 hi/lo in-kernel; 3 HMMA products per tile
// (hi*hi + hi*lo + lo*hi), fp32 accumulation.
// ---------------------------------------------------------------------------
__global__ __launch_bounds__(THREADS_G)
void gemm_split(const float* __restrict__ X, const float* __restrict__ W)
{
    // row pad 24 halves (48B = 12 words) -> conflict-free b32 fragment loads
    __shared__ __nv_bfloat16 sAh[M_ROWS][24];
    __shared__ __nv_bfloat16 sAl[M_ROWS][24];
    __shared__ __nv_bfloat16 sBh[BN][24];
    __shared__ __nv_bfloat16 sBl[BN][24];

    const int t     = threadIdx.x;
    const int n0    = blockIdx.x * BN;
    const int split = blockIdx.y;
    const int kbase = split * KCHUNK;

    // ---- A loader: 2 threads per row, 8 floats each
    const int arow  = t >> 1;
    const int ahalf = (t & 1) * 8;
    const float* aptr = X + (size_t)arow * K_DIM + kbase + ahalf;

    // ---- B loader: 16x96 tile = 1536 elems over 448 threads (<=4 each)
    int  br[4], bj[4];
    bool bv[4];
    size_t bbase[4];
    #pragma unroll
    for (int i = 0; i < 4; ++i) {
        int idx = t + i * THREADS_G;
        bv[i] = (idx < KT * BN);
        int r = bv[i] ? (idx / BN) : 0;
        int j = bv[i] ? (idx - r * BN) : 0;
        int c = n0 + j;
        int band = c / PRED;
        int p = c - band * PRED;
        br[i] = r; bj[i] = j;
        bbase[i] = ((size_t)band * K_DIM + (size_t)(kbase + r)) * PRED + p;
    }

    float va[8], vb[4];
    // prologue: load kt = 0 into registers
    {
        const float4 u0 = *reinterpret_cast<const float4*>(aptr);
        const float4 u1 = *reinterpret_cast<const float4*>(aptr + 4);
        va[0] = u0.x; va[1] = u0.y; va[2] = u0.z; va[3] = u0.w;
        va[4] = u1.x; va[5] = u1.y; va[6] = u1.z; va[7] = u1.w;
        #pragma unroll
        for (int i = 0; i < 4; ++i) vb[i] = bv[i] ? W[bbase[i]] : 0.f;
    }

    const int lane    = t & 31;
    const int warp    = t >> 5;
    const int rowbase = warp * 16;       // warp tile: rows [16w,16w+16), cols [n0,n0+96)
    const int rA      = lane >> 2;
    const int cA      = (lane & 3) * 2;

    float acc[12][4];
    #pragma unroll
    for (int nt = 0; nt < 12; ++nt) {
        acc[nt][0] = 0.f; acc[nt][1] = 0.f; acc[nt][2] = 0.f; acc[nt][3] = 0.f;
    }

    for (int kt = 0; kt < KITERS; ++kt) {
        // convert current registers -> smem (bf16 hi/lo)
        #pragma unroll
        for (int i = 0; i < 8; ++i) {
            float v = va[i];
            __nv_bfloat16 h = __float2bfloat16(v);
            __nv_bfloat16 l = __float2bfloat16(v - __bfloat162float(h));
            sAh[arow][ahalf + i] = h;
            sAl[arow][ahalf + i] = l;
        }
        #pragma unroll
        for (int i = 0; i < 4; ++i) {
            if (bv[i]) {
                float v = vb[i];
                __nv_bfloat16 h = __float2bfloat16(v);
                __nv_bfloat16 l = __float2bfloat16(v - __bfloat162float(h));
                sBh[bj[i]][br[i]] = h;   // stored transposed: [n][k]
                sBl[bj[i]][br[i]] = l;
            }
        }
        __syncthreads();

        // prefetch next k-tile into registers (overlaps with compute)
        if (kt + 1 < KITERS) {
            const float* ap = aptr + (kt + 1) * KT;
            const float4 u0 = *reinterpret_cast<const float4*>(ap);
            const float4 u1 = *reinterpret_cast<const float4*>(ap + 4);
            va[0] = u0.x; va[1] = u0.y; va[2] = u0.z; va[3] = u0.w;
            va[4] = u1.x; va[5] = u1.y; va[6] = u1.z; va[7] = u1.w;
            const size_t koff = (size_t)(kt + 1) * KT * PRED;
            #pragma unroll
            for (int i = 0; i < 4; ++i)
                vb[i] = bv[i] ? W[bbase[i] + koff] : 0.f;
        }

        // A fragments (m16n8k16 row-major layout)
        const uint32_t ah0 = ld_b32(&sAh[rowbase + rA    ][cA    ]);
        const uint32_t ah1 = ld_b32(&sAh[rowbase + rA + 8][cA    ]);
        const uint32_t ah2 = ld_b32(&sAh[rowbase + rA    ][cA + 8]);
        const uint32_t ah3 = ld_b32(&sAh[rowbase + rA + 8][cA + 8]);
        const uint32_t al0 = ld_b32(&sAl[rowbase + rA    ][cA    ]);
        const uint32_t al1 = ld_b32(&sAl[rowbase + rA + 8][cA    ]);
        const uint32_t al2 = ld_b32(&sAl[rowbase + rA    ][cA + 8]);
        const uint32_t al3 = ld_b32(&sAl[rowbase + rA + 8][cA + 8]);

        #pragma unroll
        for (int nt = 0; nt < 12; ++nt) {
            const int cn = nt * 8 + rA;
            const uint32_t bh0 = ld_b32(&sBh[cn][cA    ]);
            const uint32_t bh1 = ld_b32(&sBh[cn][cA + 8]);
            const uint32_t bl0 = ld_b32(&sBl[cn][cA    ]);
            const uint32_t bl1 = ld_b32(&sBl[cn][cA + 8]);
            MMA_BF16(acc[nt], ah0, ah1, ah2, ah3, bh0, bh1);
            MMA_BF16(acc[nt], ah0, ah1, ah2, ah3, bl0, bl1);
            MMA_BF16(acc[nt], al0, al1, al2, al3, bh0, bh1);
        }
        __syncthreads();
    }

    // epilogue -> split-K partials
    float* gp = g_part + (size_t)split * M_ROWS * NCOLS;
    const int orow = rowbase + rA;
    #pragma unroll
    for (int nt = 0; nt < 12; ++nt) {
        const int col = n0 + nt * 8 + cA;
        *reinterpret_cast<float2*>(gp + (size_t)orow * NCOLS + col) =
            make_float2(acc[nt][0], acc[nt][1]);
        *reinterpret_cast<float2*>(gp + (size_t)(orow + 8) * NCOLS + col) =
            make_float2(acc[nt][2], acc[nt][3]);
    }
}

// ---------------------------------------------------------------------------
// Split-K reduce + bias + 3-level inverse SWT (db4, periodization)
// One block per (b,n) row. Derived closed form of the reference algebra:
//   level j (step = 2^(j-1), Mlen = 336/step), strand s = t%step, m = t/step:
//     x1 = sum_k over q=(m+3-k)%Mlen even:  o[q*step+s]*RL[k] + d[q*step+s]*RH[k]
//     x2 = sum_k over q=(m+2-k)%Mlen even:  o[(q+1)*step+s]*RL[k] + d[(q+1)*step+s]*RH[k]
//     new = 0.5*(x1+x2)
// ---------------------------------------------------------------------------
__global__ void reduce_iswt(const float* __restrict__ bias, float* __restrict__ out)
{
    __shared__ float sc[4][PRED];   // sc[0] = evolving out; sc[1..3] = cD3,cD2,cD1
    const int t   = threadIdx.x;
    const int row = blockIdx.x;

    if (t < PRED) {
        #pragma unroll
        for (int band = 0; band < NBANDS; ++band) {
            float a = bias[band * PRED + t];
            const float* gp = g_part + (size_t)row * NCOLS + band * PRED + t;
            #pragma unroll
            for (int s = 0; s < SPLITS; ++s)
                a += gp[(size_t)s * M_ROWS * NCOLS];
            sc[band][t] = a;
        }
    }
    __syncthreads();

    const int steps[3] = {4, 2, 1};
    #pragma unroll
    for (int lv = 0; lv < 3; ++lv) {
        const int step = steps[lv];
        const int band = lv + 1;
        const int Mlen = PRED / step;
        float nv = 0.f;
        if (t < PRED) {
            const int s = t % step;
            const int m = t / step;
            float x1 = 0.f, x2 = 0.f;
            #pragma unroll
            for (int k = 0; k < 8; ++k) {
                int q = m + 3 - k;
                if (q >= Mlen) q -= Mlen;
                if (q < 0)     q += Mlen;
                if ((q & 1) == 0) {
                    const int idx = q * step + s;
                    x1 += sc[0][idx] * c_RL[k] + sc[band][idx] * c_RH[k];
                }
                int q2 = m + 2 - k;
                if (q2 >= Mlen) q2 -= Mlen;
                if (q2 < 0)     q2 += Mlen;
                if ((q2 & 1) == 0) {
                    const int idx2 = (q2 + 1) * step + s;
                    x2 += sc[0][idx2] * c_RL[k] + sc[band][idx2] * c_RH[k];
                }
            }
            nv = 0.5f * (x1 + x2);
        }
        __syncthreads();
        if (t < PRED) sc[0][t] = nv;
        __syncthreads();
    }

    if (t < PRED) out[(size_t)row * PRED + t] = sc[0][t];
}

// ---------------------------------------------------------------------------
extern "C" void kernel_launch(void* const* d_in, const int* in_sizes, int n_in,
                              void* d_out, int out_size)
{
    const float* X    = (const float*)d_in[0];  // (32,7,768,64) = (224, 49152)
    const float* W    = (const float*)d_in[1];  // (4, 49152, 336)
    const float* bias = (const float*)d_in[2];  // (4, 336)
    float* out        = (float*)d_out;          // (32, 7, 336)

    dim3 grid(NTILES, SPLITS);
    gemm_split<<<grid, THREADS_G>>>(X, W);
    reduce_iswt<<<M_ROWS, 352>>>(bias, out);
}